// round 5
// baseline (speedup 1.0000x reference)
#include <cuda_runtime.h>
#include <math.h>

#define MAXN   100000
#define MAXE   1600000
#define INCH   256
#define OUTCH  128
#define FSLOPE 0.01f
#define FOMEGA 0.1f
#define SCAN_B 1024
#define CHUNK  256

// ---------------- device scratch ----------------
__device__ float g_h[MAXN*OUTCH];
__device__ float g_iagg[MAXN*OUTCH];
__device__ float g_hp[MAXN*OUTCH];
__device__ float g_rowsum[MAXN];
__device__ float g_ssrc[MAXN];
__device__ float g_sdst[MAXN];
__device__ float g_asrc[INCH];
__device__ float g_adst[INCH];
__device__ float g_c1, g_c2;
__device__ float g_gamma[64*OUTCH];
__device__ float g_beta[64*OUTCH];
__device__ float g_gnorm[64];
__device__ float g_bnorm[64];
__device__ float g_bselnorm[MAXN];
__device__ int   g_degsum;
__device__ int   g_cntR;
__device__ int   g_cntNR;
__device__ int   g_work;
__device__ int   g_counts2[2*MAXN];   // [tile][src]
__device__ int   g_cursor2[2*MAXN];
__device__ int   g_bsum[256];
__device__ int   g_nodelist[MAXN];
__device__ int4  g_erec[MAXE];        // {dst, w(bits), ee(bits), src}, tile-major/src-minor

// ---------------- helpers ----------------
__device__ __forceinline__ float warp_sum(float v){
  #pragma unroll
  for(int o=16;o>0;o>>=1) v += __shfl_xor_sync(0xffffffffu, v, o);
  return v;
}
__device__ __forceinline__ int warp_sum_i(int v){
  #pragma unroll
  for(int o=16;o>0;o>>=1) v += __shfl_xor_sync(0xffffffffu, v, o);
  return v;
}
__device__ __forceinline__ unsigned long long pack2(float lo, float hi){
  unsigned long long r;
  asm("mov.b64 %0,{%1,%2};" : "=l"(r) : "f"(lo), "f"(hi));
  return r;
}
__device__ __forceinline__ void fma2(unsigned long long &d, unsigned long long a, unsigned long long b){
  asm("fma.rn.f32x2 %0, %1, %2, %0;" : "+l"(d) : "l"(a), "l"(b));
}
__device__ __forceinline__ float2 unpack2(unsigned long long p){
  float2 r;
  asm("mov.b64 {%0,%1},%2;" : "=f"(r.x), "=f"(r.y) : "l"(p));
  return r;
}
__device__ __forceinline__ void red_add_v4(float* p, float a, float b, float c, float d){
  asm volatile("red.global.add.v4.f32 [%0], {%1,%2,%3,%4};"
               :: "l"(p), "f"(a), "f"(b), "f"(c), "f"(d) : "memory");
}

// ---------------- zero accumulators ----------------
__global__ void zero_kernel(int n){
  size_t i = (size_t)blockIdx.x*blockDim.x + threadIdx.x;
  size_t stride = (size_t)gridDim.x*blockDim.x;
  float4 z = make_float4(0.f,0.f,0.f,0.f);
  float4* A = (float4*)g_iagg;
  float4* B = (float4*)g_hp;
  size_t tot4 = (size_t)n*(OUTCH/4);
  for(size_t j=i;j<tot4;j+=stride){ A[j]=z; B[j]=z; }
  for(size_t j=i;j<(size_t)n;j+=stride) g_rowsum[j]=0.f;
}

// ---------------- init counts + flags ----------------
__global__ void init_kernel(int n){
  int i = blockIdx.x*blockDim.x + threadIdx.x;
  if(i<2*n) g_counts2[i]=0;
  if(i==0){ g_degsum=0; g_cntR=0; g_cntNR=0; g_work=0; }
}

// ---------------- avec: asrc = sc*W^T a1, adst = sc*W^T a2, consts ----------------
__global__ void avec_kernel(const float* __restrict__ Ww, const float* __restrict__ wb,
                            const float* __restrict__ a){
  int k = threadIdx.x;  // 256
  float s1=0.f, s2=0.f;
  #pragma unroll 4
  for(int o=0;o<OUTCH;o++){
    float w = Ww[o*INCH + k];
    s1 = fmaf(w, a[o], s1);
    s2 = fmaf(w, a[OUTCH+o], s2);
  }
  const float sc = 11.313708498984761f;
  g_asrc[k] = s1*sc;
  g_adst[k] = s2*sc;
  __shared__ float c1s[256], c2s[256];
  float cb1=0.f, cb2=0.f;
  if(k<OUTCH){ float b=wb[k]; cb1 = b*a[k]; cb2 = b*a[OUTCH+k]; }
  c1s[k]=cb1; c2s[k]=cb2;
  __syncthreads();
  for(int s=128;s>0;s>>=1){
    if(k<s){ c1s[k]+=c1s[k+s]; c2s[k]+=c2s[k+s]; }
    __syncthreads();
  }
  if(k==0){ g_c1 = c1s[0]*sc; g_c2 = c2s[0]*sc; }
}

// ---------------- svec: s_src/s_dst = x @ asrc/adst + const ----------------
__global__ void __launch_bounds__(256) svec_kernel(const float* __restrict__ x, int n){
  int lane = threadIdx.x & 31;
  int gw = (blockIdx.x*blockDim.x + threadIdx.x) >> 5;
  int totw = (gridDim.x*blockDim.x) >> 5;
  const float4* A4 = (const float4*)g_asrc;
  const float4* B4 = (const float4*)g_adst;
  float4 A0 = A4[lane], A1 = A4[32+lane];
  float4 B0 = B4[lane], B1 = B4[32+lane];
  float c1 = g_c1, c2 = g_c2;
  const float4* x4 = (const float4*)x;
  for(int row=gw; row<n; row+=totw){
    float4 x0 = __ldg(&x4[(size_t)row*64 + lane]);
    float4 x1 = __ldg(&x4[(size_t)row*64 + 32 + lane]);
    float s1 = x0.x*A0.x + x0.y*A0.y + x0.z*A0.z + x0.w*A0.w
             + x1.x*A1.x + x1.y*A1.y + x1.z*A1.z + x1.w*A1.w;
    float s2 = x0.x*B0.x + x0.y*B0.y + x0.z*B0.z + x0.w*B0.w
             + x1.x*B1.x + x1.y*B1.y + x1.z*B1.z + x1.w*B1.w;
    s1 = warp_sum(s1);
    s2 = warp_sum(s2);
    if(lane==0){ g_ssrc[row]=s1+c1; g_sdst[row]=s2+c2; }
  }
}

// ---------------- degree sum ----------------
__global__ void degsum_kernel(const int* __restrict__ degree, int n){
  int i = blockIdx.x*blockDim.x + threadIdx.x;
  int v = (i<n) ? degree[i] : 0;
  v = warp_sum_i(v);
  if((threadIdx.x & 31)==0) atomicAdd(&g_degsum, v);
}

// ---------------- FiLM tables ----------------
__global__ void film_kernel(const float* __restrict__ PE, const float* __restrict__ Wg,
                            const float* __restrict__ Wb, const float* __restrict__ bg,
                            const float* __restrict__ bb){
  int d = blockIdx.x, c = threadIdx.x;
  float ga = bg[c], be = bb[c];
  #pragma unroll 4
  for(int k=0;k<128;k++){
    float p = PE[d*128+k];
    ga = fmaf(p, Wg[k*128+c], ga);
    be = fmaf(p, Wb[k*128+c], be);
  }
  ga = ga > 0.f ? ga : FSLOPE*ga;
  be = be > 0.f ? be : FSLOPE*be;
  g_gamma[d*128+c] = ga;
  g_beta [d*128+c] = be;
  __shared__ float sg[128], sb[128];
  sg[c] = ga*ga; sb[c] = be*be;
  __syncthreads();
  for(int s=64;s>0;s>>=1){
    if(c<s){ sg[c]+=sg[c+s]; sb[c]+=sb[c+s]; }
    __syncthreads();
  }
  if(c==0){ g_gnorm[d]=sqrtf(sg[0]); g_bnorm[d]=sqrtf(sb[0]); }
}

// ---------------- histogram over (tile, src) ----------------
__global__ void hist_kernel(const int* __restrict__ edge, int E, int nhalf, int n){
  int e = blockIdx.x*blockDim.x + threadIdx.x;
  if(e>=E) return;
  int src = edge[e];
  int dst = edge[E+e];
  int t = (dst >= nhalf) ? 1 : 0;
  atomicAdd(&g_counts2[t*n + src], 1);
}

// ---------------- scan (3 phases) over 2n counters ----------------
__global__ void scan1_kernel(int n2){
  __shared__ int red[32];
  int i = blockIdx.x*SCAN_B + threadIdx.x;
  int v = (i<n2)? g_counts2[i] : 0;
  int lane = threadIdx.x&31, w = threadIdx.x>>5;
  int s = warp_sum_i(v);
  if(lane==0) red[w]=s;
  __syncthreads();
  if(threadIdx.x<32){
    int t = red[threadIdx.x];
    t = warp_sum_i(t);
    if(threadIdx.x==0) g_bsum[blockIdx.x]=t;
  }
}
__global__ void scan2_kernel(int nb){   // nb <= 256, one block of 256
  __shared__ int ws[8];
  int t = threadIdx.x, lane = t&31, w = t>>5;
  int v = (t<nb)? g_bsum[t] : 0;
  int inc = v;
  #pragma unroll
  for(int o=1;o<32;o<<=1){ int u=__shfl_up_sync(0xffffffffu,inc,o); if(lane>=o) inc+=u; }
  if(lane==31) ws[w]=inc;
  __syncthreads();
  int off=0;
  #pragma unroll
  for(int i=0;i<8;i++) if(i<w) off+=ws[i];
  if(t<nb) g_bsum[t] = off + inc - v;
}
__global__ void scan3_kernel(int n2){
  __shared__ int wsum[32];
  int i = blockIdx.x*SCAN_B + threadIdx.x;
  int v = (i<n2)? g_counts2[i] : 0;
  int lane = threadIdx.x&31, w = threadIdx.x>>5;
  int inc = v;
  #pragma unroll
  for(int o=1;o<32;o<<=1){ int t=__shfl_up_sync(0xffffffffu,inc,o); if(lane>=o) inc+=t; }
  if(lane==31) wsum[w]=inc;
  __syncthreads();
  if(threadIdx.x<32){
    int t = wsum[threadIdx.x];
    int sc = t;
    #pragma unroll
    for(int o=1;o<32;o<<=1){ int u=__shfl_up_sync(0xffffffffu,sc,o); if(threadIdx.x>=o) sc+=u; }
    wsum[threadIdx.x] = sc - t;
  }
  __syncthreads();
  int ex = inc - v + wsum[w] + g_bsum[blockIdx.x];
  if(i<n2) g_cursor2[i]=ex;
}

// ---------------- partition nodes by R = (deg < K) ----------------
__global__ void partition_kernel(const int* __restrict__ degree, int n){
  int i = blockIdx.x*blockDim.x + threadIdx.x;
  if(i>=n) return;
  float K = (float)g_degsum/(float)n;
  int dg = degree[i];
  if((float)dg < K){ int p=atomicAdd(&g_cntR,1);  g_nodelist[p]=i; }
  else             { int p=atomicAdd(&g_cntNR,1); g_nodelist[n-1-p]=i; }
}

// ---------------- edge build: tile-major, src-minor records ----------------
__global__ void edge_build_kernel(const int* __restrict__ edge,
    const float* __restrict__ adjv, int E, int nhalf, int n){
  int e = blockIdx.x*blockDim.x + threadIdx.x;
  if(e>=E) return;
  int src = edge[e];
  int dst = edge[E+e];
  float w  = adjv[e];
  float s = g_ssrc[src] + g_sdst[dst];
  float v = s > 0.f ? s : FSLOPE*s;
  float ee = expf(-v);
  int t = (dst >= nhalf) ? 1 : 0;
  int pos = atomicAdd(&g_cursor2[t*n + src], 1);
  g_erec[pos] = make_int4(dst, __float_as_int(w), __float_as_int(ee), src);
}

// ---------------- h = sqrt(128)*(x @ Ww^T + wb) (FFMA2) ----------------
__global__ void __launch_bounds__(256) gemm_h_kernel(
    const float* __restrict__ x, const float* __restrict__ Ww,
    const float* __restrict__ wb, int n){
  __shared__ float xs[32*66];
  __shared__ float wt[32*132];
  int tid = threadIdx.x;
  int ot = tid & 31, mt = tid >> 5;
  int m0 = blockIdx.x*64;
  unsigned long long acc2[4][4];
  #pragma unroll
  for(int i=0;i<4;i++)
    #pragma unroll
    for(int j=0;j<4;j++) acc2[i][j]=0ull;

  for(int kc=0;kc<8;kc++){
    #pragma unroll
    for(int i=0;i<2;i++){
      int e = tid + 256*i;
      int m = e>>3, k4 = e&7;
      int gm = m0+m;
      float4 v = make_float4(0.f,0.f,0.f,0.f);
      if(gm<n) v = *(const float4*)&x[(size_t)gm*INCH + kc*32 + k4*4];
      xs[(k4*4+0)*66 + m]=v.x; xs[(k4*4+1)*66 + m]=v.y;
      xs[(k4*4+2)*66 + m]=v.z; xs[(k4*4+3)*66 + m]=v.w;
    }
    #pragma unroll
    for(int i=0;i<4;i++){
      int e = tid + 256*i;
      int o = e>>3, k4 = e&7;
      float4 v = *(const float4*)&Ww[(size_t)o*INCH + kc*32 + k4*4];
      wt[(k4*4+0)*132 + o]=v.x; wt[(k4*4+1)*132 + o]=v.y;
      wt[(k4*4+2)*132 + o]=v.z; wt[(k4*4+3)*132 + o]=v.w;
    }
    __syncthreads();
    #pragma unroll 4
    for(int k=0;k<32;k++){
      float4 wv = *(const float4*)&wt[k*132 + ot*4];
      unsigned long long wp0=pack2(wv.x,wv.x), wp1=pack2(wv.y,wv.y);
      unsigned long long wp2=pack2(wv.z,wv.z), wp3=pack2(wv.w,wv.w);
      #pragma unroll
      for(int i=0;i<4;i++){
        unsigned long long xp = *(const unsigned long long*)&xs[k*66 + mt*8 + 2*i];
        fma2(acc2[i][0], xp, wp0);
        fma2(acc2[i][1], xp, wp1);
        fma2(acc2[i][2], xp, wp2);
        fma2(acc2[i][3], xp, wp3);
      }
    }
    __syncthreads();
  }
  const float sc = 11.313708498984761f;
  float4 bv = *(const float4*)&wb[ot*4];
  #pragma unroll
  for(int i=0;i<4;i++){
    float2 c0 = unpack2(acc2[i][0]);
    float2 c1 = unpack2(acc2[i][1]);
    float2 c2 = unpack2(acc2[i][2]);
    float2 c3 = unpack2(acc2[i][3]);
    #pragma unroll
    for(int p=0;p<2;p++){
      int m = m0 + mt*8 + 2*i + p;
      if(m<n){
        float h0 = ((p? c0.y:c0.x)+bv.x)*sc;
        float h1 = ((p? c1.y:c1.x)+bv.y)*sc;
        float h2 = ((p? c2.y:c2.x)+bv.z)*sc;
        float h3 = ((p? c3.y:c3.x)+bv.w)*sc;
        *(float4*)&g_h[(size_t)m*OUTCH + ot*4] = make_float4(h0,h1,h2,h3);
      }
    }
  }
}

// ---------------- edge-centric segmented aggregation (work-queue chunks) ----------------
struct AggState {
  unsigned long long ai01, ai23, p01, p23;
  float rs;
  int cur;
};
__device__ __forceinline__ void agg_flush(AggState& st, int lane){
  float2 u0=unpack2(st.ai01), u1=unpack2(st.ai23);
  float2 v0=unpack2(st.p01),  v1=unpack2(st.p23);
  red_add_v4(&g_iagg[(size_t)st.cur*OUTCH + lane*4], u0.x,u0.y,u1.x,u1.y);
  red_add_v4(&g_hp  [(size_t)st.cur*OUTCH + lane*4], v0.x,v0.y,v1.x,v1.y);
  if(lane==0) atomicAdd(&g_rowsum[st.cur], st.rs);
}
__device__ __forceinline__ void agg_proc(AggState& st, int4 r, float4 h, int lane){
  if(r.w != st.cur){
    if(st.cur>=0) agg_flush(st, lane);
    st.cur=r.w; st.ai01=0ull; st.ai23=0ull; st.p01=0ull; st.p23=0ull; st.rs=0.f;
  }
  float wf = __int_as_float(r.y), ef = __int_as_float(r.z);
  unsigned long long h01=pack2(h.x,h.y), h23=pack2(h.z,h.w);
  unsigned long long wp=pack2(wf,wf), ep=pack2(ef,ef);
  fma2(st.ai01,h01,wp); fma2(st.ai23,h23,wp);
  fma2(st.p01, h01,ep); fma2(st.p23, h23,ep);
  st.rs += ef;
}
__global__ void __launch_bounds__(256) agg_edge_kernel(int E){
  int lane = threadIdx.x & 31;
  for(;;){
    int c;
    if(lane==0) c = atomicAdd(&g_work, 1);
    c = __shfl_sync(0xffffffffu, c, 0);
    int e0 = c*CHUNK;
    if(e0 >= E) break;
    int e1 = min(E, e0 + CHUNK);
    AggState st; st.cur = -1; st.ai01=0; st.ai23=0; st.p01=0; st.p23=0; st.rs=0.f;
    int q = e0;
    for(; q+4<=e1; q+=4){
      int4 r0 = __ldg(&g_erec[q+0]);
      int4 r1 = __ldg(&g_erec[q+1]);
      int4 r2 = __ldg(&g_erec[q+2]);
      int4 r3 = __ldg(&g_erec[q+3]);
      float4 h0 = *(const float4*)&g_h[(size_t)r0.x*OUTCH + lane*4];
      float4 h1 = *(const float4*)&g_h[(size_t)r1.x*OUTCH + lane*4];
      float4 h2 = *(const float4*)&g_h[(size_t)r2.x*OUTCH + lane*4];
      float4 h3 = *(const float4*)&g_h[(size_t)r3.x*OUTCH + lane*4];
      agg_proc(st, r0, h0, lane);
      agg_proc(st, r1, h1, lane);
      agg_proc(st, r2, h2, lane);
      agg_proc(st, r3, h3, lane);
    }
    for(; q<e1; q++){
      int4 r0 = __ldg(&g_erec[q]);
      float4 h0 = *(const float4*)&g_h[(size_t)r0.x*OUTCH + lane*4];
      agg_proc(st, r0, h0, lane);
    }
    if(st.cur>=0) agg_flush(st, lane);
  }
}

// ---------------- finalize: batched-8 selected matvec (FFMA2) ----------------
__global__ void __launch_bounds__(256) finalize2_kernel(
    const float* __restrict__ Wadd, const float* __restrict__ Wrev,
    const int* __restrict__ degree, float* __restrict__ out, int n){
  extern __shared__ float sm[];
  float* waT   = sm;                   // 128*132
  float* wrT   = sm + 128*132;         // 128*132
  float* stage = sm + 2*128*132;       // 8 warps * 1024  ([k][j8])
  int tid = threadIdx.x;
  int ot = tid & 31, wid = tid >> 5;
  #pragma unroll
  for(int i=0;i<16;i++){
    int e2 = tid + 256*i;
    int o = e2>>5, k4 = e2&31;
    float4 va = *(const float4*)&Wadd[o*128 + k4*4];
    float4 vr = *(const float4*)&Wrev[o*128 + k4*4];
    waT[(k4*4+0)*132+o]=va.x; waT[(k4*4+1)*132+o]=va.y;
    waT[(k4*4+2)*132+o]=va.z; waT[(k4*4+3)*132+o]=va.w;
    wrT[(k4*4+0)*132+o]=vr.x; wrT[(k4*4+1)*132+o]=vr.y;
    wrT[(k4*4+2)*132+o]=vr.z; wrT[(k4*4+3)*132+o]=vr.w;
  }
  __syncthreads();
  float K = (float)g_degsum/(float)n;
  float* st = stage + wid*1024;
  int j8 = ot & 7;
  int kb = (ot>>3)*32;
  int gwarp = blockIdx.x*8 + wid;
  int nbatch = (n+7)/8;
  int totw = gridDim.x*8;
  for(int b=gwarp; b<nbatch; b+=totw){
    int base = b*8;
    {
      int idx = base + j8;
      int node = g_nodelist[idx < n ? idx : n-1];
      int dg = __ldg(&degree[node]);
      float dinv = dg>0 ? 1.f/(float)dg : 0.f;
      #pragma unroll
      for(int r=0;r<8;r++){
        int kk = kb + r*4;
        float4 v = *(const float4*)&g_iagg[(size_t)node*OUTCH + kk];
        st[(kk+0)*8 + j8]=v.x*dinv; st[(kk+1)*8 + j8]=v.y*dinv;
        st[(kk+2)*8 + j8]=v.z*dinv; st[(kk+3)*8 + j8]=v.w*dinv;
      }
    }
    unsigned rmask=0, vmask=0;
    #pragma unroll
    for(int j=0;j<8;j++){
      int idx = base+j;
      if(idx<n){
        vmask |= 1u<<j;
        int nd = g_nodelist[idx];
        int dg = __ldg(&degree[nd]);
        if((float)dg < K) rmask |= 1u<<j;
      }
    }
    __syncwarp();
    #pragma unroll
    for(int pass=0; pass<2; pass++){
      unsigned sel = pass ? ((~rmask)&vmask) : (rmask&vmask);
      if(!sel) continue;
      const float* W = pass ? wrT : waT;
      unsigned long long acc2[4][4];
      #pragma unroll
      for(int i=0;i<4;i++)
        #pragma unroll
        for(int c=0;c<4;c++) acc2[i][c]=0ull;
      #pragma unroll 4
      for(int k=0;k<128;k++){
        float4 wv = *(const float4*)&W[k*132 + ot*4];
        unsigned long long wp0=pack2(wv.x,wv.x), wp1=pack2(wv.y,wv.y);
        unsigned long long wp2=pack2(wv.z,wv.z), wp3=pack2(wv.w,wv.w);
        #pragma unroll
        for(int i=0;i<4;i++){
          unsigned long long xp = *(const unsigned long long*)&st[k*8 + 2*i];
          fma2(acc2[i][0], xp, wp0);
          fma2(acc2[i][1], xp, wp1);
          fma2(acc2[i][2], xp, wp2);
          fma2(acc2[i][3], xp, wp3);
        }
      }
      float sgn = pass ? -FOMEGA : FOMEGA;
      #pragma unroll
      for(int j=0;j<8;j++){
        if(!((sel>>j)&1u)) continue;
        int nd = g_nodelist[base+j];
        int i = j>>1, p = j&1;
        float2 u0 = unpack2(acc2[i][0]);
        float2 u1 = unpack2(acc2[i][1]);
        float2 u2 = unpack2(acc2[i][2]);
        float2 u3 = unpack2(acc2[i][3]);
        float a0 = p? u0.y:u0.x;
        float a1 = p? u1.y:u1.x;
        float a2 = p? u2.y:u2.x;
        float a3 = p? u3.y:u3.x;
        int dg = __ldg(&degree[nd]);
        int dt = dg<0?0:(dg>63?63:dg);
        float4 gv = *(const float4*)&g_gamma[dt*128 + ot*4];
        float4 bv = *(const float4*)&g_beta [dt*128 + ot*4];
        float b0 = fmaf(gv.x+1.f, a0, bv.x);
        float b1 = fmaf(gv.y+1.f, a1, bv.y);
        float b2 = fmaf(gv.z+1.f, a2, bv.z);
        float b3 = fmaf(gv.w+1.f, a3, bv.w);
        float rs = g_rowsum[nd];
        float dn = 1.f/(rs + 1.00001f);
        float4 hp = *(const float4*)&g_hp[(size_t)nd*OUTCH + ot*4];
        float ss = b0*b0 + b1*b1 + b2*b2 + b3*b3;
        ss = warp_sum(ss);
        float4 ov = make_float4((hp.x + sgn*b0)*dn, (hp.y + sgn*b1)*dn,
                                (hp.z + sgn*b2)*dn, (hp.w + sgn*b3)*dn);
        *(float4*)&out[(size_t)nd*OUTCH + ot*4] = ov;
        if(ot==0) g_bselnorm[nd] = sqrtf(ss);
      }
    }
    __syncwarp();
  }
}

// ---------------- losses over idx ----------------
__global__ void loss_kernel(const int* __restrict__ idx, const int* __restrict__ degree,
                            float* __restrict__ outs, int nidx){
  float lb=0.f, lf=0.f;
  for(int j = threadIdx.x; j < nidx; j += blockDim.x){
    int nn = idx[j];
    lb += g_bselnorm[nn];
    int d = degree[nn];
    d = d < 0 ? 0 : (d > 63 ? 63 : d);
    lf += g_gnorm[d] + g_bnorm[d];
  }
  __shared__ float s1[512], s2[512];
  s1[threadIdx.x]=lb; s2[threadIdx.x]=lf;
  __syncthreads();
  for(int s=256;s>0;s>>=1){
    if(threadIdx.x<s){ s1[threadIdx.x]+=s1[threadIdx.x+s]; s2[threadIdx.x]+=s2[threadIdx.x+s]; }
    __syncthreads();
  }
  if(threadIdx.x==0){
    float inv = 1.f/(float)nidx;
    outs[0] = s1[0]*inv;
    outs[1] = s2[0]*inv;
  }
}

extern "C" void kernel_launch(void* const* d_in, const int* in_sizes, int n_in,
                              void* d_out, int out_size){
  const float* x     = (const float*)d_in[0];
  const int*   edge  = (const int*)  d_in[1];
  const float* adjv  = (const float*)d_in[2];
  const int*   degree= (const int*)  d_in[3];
  const int*   idx   = (const int*)  d_in[4];
  const float* Ww    = (const float*)d_in[5];
  const float* wbb   = (const float*)d_in[6];
  const float* av    = (const float*)d_in[7];
  const float* Wg    = (const float*)d_in[8];
  const float* Wb    = (const float*)d_in[9];
  const float* bg    = (const float*)d_in[10];
  const float* bb    = (const float*)d_in[11];
  const float* Wadd  = (const float*)d_in[12];
  const float* Wrev  = (const float*)d_in[13];
  const float* PE    = (const float*)d_in[14];
  int n    = in_sizes[0] / INCH;
  int E    = in_sizes[2];
  int nidx = in_sizes[4];
  int nhalf = n >> 1;
  float* out = (float*)d_out;
  int n2 = 2*n;
  int nb = (n2 + SCAN_B - 1)/SCAN_B;

  static cudaStream_t s_side = 0;
  static cudaEvent_t ev_fork = 0, ev_join = 0;
  static int made = 0;
  if(!made){
    cudaStreamCreateWithFlags(&s_side, cudaStreamNonBlocking);
    cudaEventCreateWithFlags(&ev_fork, cudaEventDisableTiming);
    cudaEventCreateWithFlags(&ev_join, cudaEventDisableTiming);
    made = 1;
  }

  size_t fsmem = (size_t)(2*128*132 + 8*1024)*sizeof(float);
  cudaFuncSetAttribute(finalize2_kernel, cudaFuncAttributeMaxDynamicSharedMemorySize, (int)fsmem);

  // fork: everything except gemm_h runs on the side stream, overlapped
  cudaEventRecord(ev_fork, 0);
  cudaStreamWaitEvent(s_side, ev_fork, 0);

  zero_kernel<<<1184, 256, 0, s_side>>>(n);
  init_kernel<<<(n2+255)/256, 256, 0, s_side>>>(n);
  avec_kernel<<<1, 256, 0, s_side>>>(Ww, wbb, av);
  svec_kernel<<<512, 256, 0, s_side>>>(x, n);
  degsum_kernel<<<(n+255)/256, 256, 0, s_side>>>(degree, n);
  film_kernel<<<64, 128, 0, s_side>>>(PE, Wg, Wb, bg, bb);
  hist_kernel<<<(E+255)/256, 256, 0, s_side>>>(edge, E, nhalf, n);
  scan1_kernel<<<nb, SCAN_B, 0, s_side>>>(n2);
  scan2_kernel<<<1, 256, 0, s_side>>>(nb);
  scan3_kernel<<<nb, SCAN_B, 0, s_side>>>(n2);
  partition_kernel<<<(n+255)/256, 256, 0, s_side>>>(degree, n);
  edge_build_kernel<<<(E+255)/256, 256, 0, s_side>>>(edge, adjv, E, nhalf, n);

  gemm_h_kernel<<<(n+63)/64, 256>>>(x, Ww, wbb, n);

  // join: agg needs g_h (main) + erec/zeroed buffers (side)
  cudaEventRecord(ev_join, s_side);
  cudaStreamWaitEvent(0, ev_join, 0);

  agg_edge_kernel<<<592, 256>>>(E);
  finalize2_kernel<<<304, 256, fsmem>>>(Wadd, Wrev, degree, out, n);
  loss_kernel<<<1, 512>>>(idx, degree, out + (size_t)n*OUTCH, nidx);
}

// round 6
// speedup vs baseline: 1.1122x; 1.1122x over previous
#include <cuda_runtime.h>
#include <math.h>

#define MAXN   100000
#define MAXE   1600000
#define INCH   256
#define OUTCH  128
#define FSLOPE 0.01f
#define FOMEGA 0.1f
#define SCAN_B 1024

// ---------------- device scratch ----------------
__device__ float g_h[MAXN*OUTCH];
__device__ float g_iagg[MAXN*OUTCH];
__device__ float g_hp[MAXN*OUTCH];
__device__ float g_rowsum[MAXN];
__device__ float g_ssrc[MAXN];
__device__ float g_sdst[MAXN];
__device__ float g_asrc[INCH];
__device__ float g_adst[INCH];
__device__ float g_c1, g_c2;
__device__ float g_gamma[64*OUTCH];
__device__ float g_beta[64*OUTCH];
__device__ float g_gnorm[64];
__device__ float g_bnorm[64];
__device__ float g_bselnorm[MAXN];
__device__ int   g_degsum;
__device__ int   g_cntR;
__device__ int   g_cntNR;
__device__ int   g_t0end;            // # edges in tile 0 (dst < nhalf)
__device__ int   g_counts2[2*MAXN];  // [tile][src]
__device__ int   g_cursor2[2*MAXN];
__device__ int   g_bsum[256];
__device__ int   g_nodelist[MAXN];
__device__ int4  g_erec[MAXE];       // {dst, w(bits), ee(bits), src}, tile-major/src-minor

// ---------------- helpers ----------------
__device__ __forceinline__ float warp_sum(float v){
  #pragma unroll
  for(int o=16;o>0;o>>=1) v += __shfl_xor_sync(0xffffffffu, v, o);
  return v;
}
__device__ __forceinline__ int warp_sum_i(int v){
  #pragma unroll
  for(int o=16;o>0;o>>=1) v += __shfl_xor_sync(0xffffffffu, v, o);
  return v;
}
__device__ __forceinline__ unsigned long long pack2(float lo, float hi){
  unsigned long long r;
  asm("mov.b64 %0,{%1,%2};" : "=l"(r) : "f"(lo), "f"(hi));
  return r;
}
__device__ __forceinline__ void fma2(unsigned long long &d, unsigned long long a, unsigned long long b){
  asm("fma.rn.f32x2 %0, %1, %2, %0;" : "+l"(d) : "l"(a), "l"(b));
}
__device__ __forceinline__ float2 unpack2(unsigned long long p){
  float2 r;
  asm("mov.b64 {%0,%1},%2;" : "=f"(r.x), "=f"(r.y) : "l"(p));
  return r;
}
__device__ __forceinline__ void red_add_v4(float* p, float a, float b, float c, float d){
  asm volatile("red.global.add.v4.f32 [%0], {%1,%2,%3,%4};"
               :: "l"(p), "f"(a), "f"(b), "f"(c), "f"(d) : "memory");
}

// ---------------- zero accumulators ----------------
__global__ void zero_kernel(int n){
  size_t i = (size_t)blockIdx.x*blockDim.x + threadIdx.x;
  size_t stride = (size_t)gridDim.x*blockDim.x;
  float4 z = make_float4(0.f,0.f,0.f,0.f);
  float4* A = (float4*)g_iagg;
  float4* B = (float4*)g_hp;
  size_t tot4 = (size_t)n*(OUTCH/4);
  for(size_t j=i;j<tot4;j+=stride){ A[j]=z; B[j]=z; }
  for(size_t j=i;j<(size_t)n;j+=stride) g_rowsum[j]=0.f;
}

// ---------------- init counts + flags ----------------
__global__ void init_kernel(int n){
  int i = blockIdx.x*blockDim.x + threadIdx.x;
  if(i<2*n) g_counts2[i]=0;
  if(i==0){ g_degsum=0; g_cntR=0; g_cntNR=0; }
}

// ---------------- avec: asrc = sc*W^T a1, adst = sc*W^T a2, consts ----------------
__global__ void avec_kernel(const float* __restrict__ Ww, const float* __restrict__ wb,
                            const float* __restrict__ a){
  int k = threadIdx.x;  // 256
  float s1=0.f, s2=0.f;
  #pragma unroll 4
  for(int o=0;o<OUTCH;o++){
    float w = Ww[o*INCH + k];
    s1 = fmaf(w, a[o], s1);
    s2 = fmaf(w, a[OUTCH+o], s2);
  }
  const float sc = 11.313708498984761f;
  g_asrc[k] = s1*sc;
  g_adst[k] = s2*sc;
  __shared__ float c1s[256], c2s[256];
  float cb1=0.f, cb2=0.f;
  if(k<OUTCH){ float b=wb[k]; cb1 = b*a[k]; cb2 = b*a[OUTCH+k]; }
  c1s[k]=cb1; c2s[k]=cb2;
  __syncthreads();
  for(int s=128;s>0;s>>=1){
    if(k<s){ c1s[k]+=c1s[k+s]; c2s[k]+=c2s[k+s]; }
    __syncthreads();
  }
  if(k==0){ g_c1 = c1s[0]*sc; g_c2 = c2s[0]*sc; }
}

// ---------------- svec: s_src/s_dst = x @ asrc/adst + const ----------------
__global__ void __launch_bounds__(256) svec_kernel(const float* __restrict__ x, int n){
  int lane = threadIdx.x & 31;
  int gw = (blockIdx.x*blockDim.x + threadIdx.x) >> 5;
  int totw = (gridDim.x*blockDim.x) >> 5;
  const float4* A4 = (const float4*)g_asrc;
  const float4* B4 = (const float4*)g_adst;
  float4 A0 = A4[lane], A1 = A4[32+lane];
  float4 B0 = B4[lane], B1 = B4[32+lane];
  float c1 = g_c1, c2 = g_c2;
  const float4* x4 = (const float4*)x;
  for(int row=gw; row<n; row+=totw){
    float4 x0 = __ldg(&x4[(size_t)row*64 + lane]);
    float4 x1 = __ldg(&x4[(size_t)row*64 + 32 + lane]);
    float s1 = x0.x*A0.x + x0.y*A0.y + x0.z*A0.z + x0.w*A0.w
             + x1.x*A1.x + x1.y*A1.y + x1.z*A1.z + x1.w*A1.w;
    float s2 = x0.x*B0.x + x0.y*B0.y + x0.z*B0.z + x0.w*B0.w
             + x1.x*B1.x + x1.y*B1.y + x1.z*B1.z + x1.w*B1.w;
    s1 = warp_sum(s1);
    s2 = warp_sum(s2);
    if(lane==0){ g_ssrc[row]=s1+c1; g_sdst[row]=s2+c2; }
  }
}

// ---------------- degree sum ----------------
__global__ void degsum_kernel(const int* __restrict__ degree, int n){
  int i = blockIdx.x*blockDim.x + threadIdx.x;
  int v = (i<n) ? degree[i] : 0;
  v = warp_sum_i(v);
  if((threadIdx.x & 31)==0) atomicAdd(&g_degsum, v);
}

// ---------------- FiLM tables ----------------
__global__ void film_kernel(const float* __restrict__ PE, const float* __restrict__ Wg,
                            const float* __restrict__ Wb, const float* __restrict__ bg,
                            const float* __restrict__ bb){
  int d = blockIdx.x, c = threadIdx.x;
  float ga = bg[c], be = bb[c];
  #pragma unroll 4
  for(int k=0;k<128;k++){
    float p = PE[d*128+k];
    ga = fmaf(p, Wg[k*128+c], ga);
    be = fmaf(p, Wb[k*128+c], be);
  }
  ga = ga > 0.f ? ga : FSLOPE*ga;
  be = be > 0.f ? be : FSLOPE*be;
  g_gamma[d*128+c] = ga;
  g_beta [d*128+c] = be;
  __shared__ float sg[128], sb[128];
  sg[c] = ga*ga; sb[c] = be*be;
  __syncthreads();
  for(int s=64;s>0;s>>=1){
    if(c<s){ sg[c]+=sg[c+s]; sb[c]+=sb[c+s]; }
    __syncthreads();
  }
  if(c==0){ g_gnorm[d]=sqrtf(sg[0]); g_bnorm[d]=sqrtf(sb[0]); }
}

// ---------------- histogram over (tile, src) ----------------
__global__ void hist_kernel(const int* __restrict__ edge, int E, int nhalf, int n){
  int e = blockIdx.x*blockDim.x + threadIdx.x;
  if(e>=E) return;
  int src = edge[e];
  int dst = edge[E+e];
  int t = (dst >= nhalf) ? 1 : 0;
  atomicAdd(&g_counts2[t*n + src], 1);
}

// ---------------- scan (3 phases) over 2n counters ----------------
__global__ void scan1_kernel(int n2){
  __shared__ int red[32];
  int i = blockIdx.x*SCAN_B + threadIdx.x;
  int v = (i<n2)? g_counts2[i] : 0;
  int lane = threadIdx.x&31, w = threadIdx.x>>5;
  int s = warp_sum_i(v);
  if(lane==0) red[w]=s;
  __syncthreads();
  if(threadIdx.x<32){
    int t = red[threadIdx.x];
    t = warp_sum_i(t);
    if(threadIdx.x==0) g_bsum[blockIdx.x]=t;
  }
}
__global__ void scan2_kernel(int nb){   // nb <= 256, one block of 256
  __shared__ int ws[8];
  int t = threadIdx.x, lane = t&31, w = t>>5;
  int v = (t<nb)? g_bsum[t] : 0;
  int inc = v;
  #pragma unroll
  for(int o=1;o<32;o<<=1){ int u=__shfl_up_sync(0xffffffffu,inc,o); if(lane>=o) inc+=u; }
  if(lane==31) ws[w]=inc;
  __syncthreads();
  int off=0;
  #pragma unroll
  for(int i=0;i<8;i++) if(i<w) off+=ws[i];
  if(t<nb) g_bsum[t] = off + inc - v;
}
__global__ void scan3_kernel(int n2, int n){
  __shared__ int wsum[32];
  int i = blockIdx.x*SCAN_B + threadIdx.x;
  int v = (i<n2)? g_counts2[i] : 0;
  int lane = threadIdx.x&31, w = threadIdx.x>>5;
  int inc = v;
  #pragma unroll
  for(int o=1;o<32;o<<=1){ int t=__shfl_up_sync(0xffffffffu,inc,o); if(lane>=o) inc+=t; }
  if(lane==31) wsum[w]=inc;
  __syncthreads();
  if(threadIdx.x<32){
    int t = wsum[threadIdx.x];
    int sc = t;
    #pragma unroll
    for(int o=1;o<32;o<<=1){ int u=__shfl_up_sync(0xffffffffu,sc,o); if(threadIdx.x>=o) sc+=u; }
    wsum[threadIdx.x] = sc - t;
  }
  __syncthreads();
  int ex = inc - v + wsum[w] + g_bsum[blockIdx.x];
  if(i<n2) g_cursor2[i]=ex;
  if(i==n) g_t0end = ex;   // exclusive prefix at (tile1,src0) = #edges in tile 0
}

// ---------------- partition nodes by R = (deg < K) ----------------
__global__ void partition_kernel(const int* __restrict__ degree, int n){
  int i = blockIdx.x*blockDim.x + threadIdx.x;
  if(i>=n) return;
  float K = (float)g_degsum/(float)n;
  int dg = degree[i];
  if((float)dg < K){ int p=atomicAdd(&g_cntR,1);  g_nodelist[p]=i; }
  else             { int p=atomicAdd(&g_cntNR,1); g_nodelist[n-1-p]=i; }
}

// ---------------- edge build: tile-major, src-minor records ----------------
__global__ void edge_build_kernel(const int* __restrict__ edge,
    const float* __restrict__ adjv, int E, int nhalf, int n){
  int e = blockIdx.x*blockDim.x + threadIdx.x;
  if(e>=E) return;
  int src = edge[e];
  int dst = edge[E+e];
  float w  = adjv[e];
  float s = g_ssrc[src] + g_sdst[dst];
  float v = s > 0.f ? s : FSLOPE*s;
  float ee = expf(-v);
  int t = (dst >= nhalf) ? 1 : 0;
  int pos = atomicAdd(&g_cursor2[t*n + src], 1);
  g_erec[pos] = make_int4(dst, __float_as_int(w), __float_as_int(ee), src);
}

// ---------------- h = sqrt(128)*(x @ Ww^T + wb) (FFMA2), row range [r0,r1) ----------------
__global__ void __launch_bounds__(256) gemm_h_kernel(
    const float* __restrict__ x, const float* __restrict__ Ww,
    const float* __restrict__ wb, int r0, int r1){
  __shared__ float xs[32*66];
  __shared__ float wt[32*132];
  int tid = threadIdx.x;
  int ot = tid & 31, mt = tid >> 5;
  int m0 = r0 + blockIdx.x*64;
  unsigned long long acc2[4][4];
  #pragma unroll
  for(int i=0;i<4;i++)
    #pragma unroll
    for(int j=0;j<4;j++) acc2[i][j]=0ull;

  for(int kc=0;kc<8;kc++){
    #pragma unroll
    for(int i=0;i<2;i++){
      int e = tid + 256*i;
      int m = e>>3, k4 = e&7;
      int gm = m0+m;
      float4 v = make_float4(0.f,0.f,0.f,0.f);
      if(gm<r1) v = *(const float4*)&x[(size_t)gm*INCH + kc*32 + k4*4];
      xs[(k4*4+0)*66 + m]=v.x; xs[(k4*4+1)*66 + m]=v.y;
      xs[(k4*4+2)*66 + m]=v.z; xs[(k4*4+3)*66 + m]=v.w;
    }
    #pragma unroll
    for(int i=0;i<4;i++){
      int e = tid + 256*i;
      int o = e>>3, k4 = e&7;
      float4 v = *(const float4*)&Ww[(size_t)o*INCH + kc*32 + k4*4];
      wt[(k4*4+0)*132 + o]=v.x; wt[(k4*4+1)*132 + o]=v.y;
      wt[(k4*4+2)*132 + o]=v.z; wt[(k4*4+3)*132 + o]=v.w;
    }
    __syncthreads();
    #pragma unroll 4
    for(int k=0;k<32;k++){
      float4 wv = *(const float4*)&wt[k*132 + ot*4];
      unsigned long long wp0=pack2(wv.x,wv.x), wp1=pack2(wv.y,wv.y);
      unsigned long long wp2=pack2(wv.z,wv.z), wp3=pack2(wv.w,wv.w);
      #pragma unroll
      for(int i=0;i<4;i++){
        unsigned long long xp = *(const unsigned long long*)&xs[k*66 + mt*8 + 2*i];
        fma2(acc2[i][0], xp, wp0);
        fma2(acc2[i][1], xp, wp1);
        fma2(acc2[i][2], xp, wp2);
        fma2(acc2[i][3], xp, wp3);
      }
    }
    __syncthreads();
  }
  const float sc = 11.313708498984761f;
  float4 bv = *(const float4*)&wb[ot*4];
  #pragma unroll
  for(int i=0;i<4;i++){
    float2 c0 = unpack2(acc2[i][0]);
    float2 c1 = unpack2(acc2[i][1]);
    float2 c2 = unpack2(acc2[i][2]);
    float2 c3 = unpack2(acc2[i][3]);
    #pragma unroll
    for(int p=0;p<2;p++){
      int m = m0 + mt*8 + 2*i + p;
      if(m<r1){
        float h0 = ((p? c0.y:c0.x)+bv.x)*sc;
        float h1 = ((p? c1.y:c1.x)+bv.y)*sc;
        float h2 = ((p? c2.y:c2.x)+bv.z)*sc;
        float h3 = ((p? c3.y:c3.x)+bv.w)*sc;
        *(float4*)&g_h[(size_t)m*OUTCH + ot*4] = make_float4(h0,h1,h2,h3);
      }
    }
  }
}

// ---------------- edge-centric segmented aggregation (per dst-tile, static) ----------------
struct AggState {
  unsigned long long ai01, ai23, p01, p23;
  float rs;
  int cur;
};
__device__ __forceinline__ void agg_flush(AggState& st, int lane){
  float2 u0=unpack2(st.ai01), u1=unpack2(st.ai23);
  float2 v0=unpack2(st.p01),  v1=unpack2(st.p23);
  red_add_v4(&g_iagg[(size_t)st.cur*OUTCH + lane*4], u0.x,u0.y,u1.x,u1.y);
  red_add_v4(&g_hp  [(size_t)st.cur*OUTCH + lane*4], v0.x,v0.y,v1.x,v1.y);
  if(lane==0) atomicAdd(&g_rowsum[st.cur], st.rs);
}
__device__ __forceinline__ void agg_proc(AggState& st, int4 r, float4 h, int lane){
  if(r.w != st.cur){
    if(st.cur>=0) agg_flush(st, lane);
    st.cur=r.w; st.ai01=0ull; st.ai23=0ull; st.p01=0ull; st.p23=0ull; st.rs=0.f;
  }
  float wf = __int_as_float(r.y), ef = __int_as_float(r.z);
  unsigned long long h01=pack2(h.x,h.y), h23=pack2(h.z,h.w);
  unsigned long long wp=pack2(wf,wf), ep=pack2(ef,ef);
  fma2(st.ai01,h01,wp); fma2(st.ai23,h23,wp);
  fma2(st.p01, h01,ep); fma2(st.p23, h23,ep);
  st.rs += ef;
}
__global__ void __launch_bounds__(512) agg_edge_kernel(int tile, int E){
  int t0 = g_t0end;
  int e_lo = tile ? t0 : 0;
  int e_hi = tile ? E  : t0;
  int nE = e_hi - e_lo;
  if(nE <= 0) return;
  int lane = threadIdx.x & 31;
  int gw = (blockIdx.x*blockDim.x + threadIdx.x) >> 5;
  int totw = (gridDim.x*blockDim.x) >> 5;
  int C = (((nE + totw - 1)/totw) + 3) & ~3;
  int e0 = e_lo + gw*C;
  int e1 = min(e_hi, e0 + C);
  if(e0 >= e1) return;
  AggState st; st.cur = -1; st.ai01=0; st.ai23=0; st.p01=0; st.p23=0; st.rs=0.f;
  int q = e0;
  for(; q+4<=e1; q+=4){
    int4 r0 = __ldg(&g_erec[q+0]);
    int4 r1 = __ldg(&g_erec[q+1]);
    int4 r2 = __ldg(&g_erec[q+2]);
    int4 r3 = __ldg(&g_erec[q+3]);
    float4 h0 = *(const float4*)&g_h[(size_t)r0.x*OUTCH + lane*4];
    float4 h1 = *(const float4*)&g_h[(size_t)r1.x*OUTCH + lane*4];
    float4 h2 = *(const float4*)&g_h[(size_t)r2.x*OUTCH + lane*4];
    float4 h3 = *(const float4*)&g_h[(size_t)r3.x*OUTCH + lane*4];
    agg_proc(st, r0, h0, lane);
    agg_proc(st, r1, h1, lane);
    agg_proc(st, r2, h2, lane);
    agg_proc(st, r3, h3, lane);
  }
  for(; q<e1; q++){
    int4 r0 = __ldg(&g_erec[q]);
    float4 h0 = *(const float4*)&g_h[(size_t)r0.x*OUTCH + lane*4];
    agg_proc(st, r0, h0, lane);
  }
  if(st.cur>=0) agg_flush(st, lane);
}

// ---------------- finalize: batched-8 selected matvec (FFMA2) ----------------
__global__ void __launch_bounds__(256) finalize2_kernel(
    const float* __restrict__ Wadd, const float* __restrict__ Wrev,
    const int* __restrict__ degree, float* __restrict__ out, int n){
  extern __shared__ float sm[];
  float* waT   = sm;                   // 128*132
  float* wrT   = sm + 128*132;         // 128*132
  float* stage = sm + 2*128*132;       // 8 warps * 1024  ([k][j8])
  int tid = threadIdx.x;
  int ot = tid & 31, wid = tid >> 5;
  #pragma unroll
  for(int i=0;i<16;i++){
    int e2 = tid + 256*i;
    int o = e2>>5, k4 = e2&31;
    float4 va = *(const float4*)&Wadd[o*128 + k4*4];
    float4 vr = *(const float4*)&Wrev[o*128 + k4*4];
    waT[(k4*4+0)*132+o]=va.x; waT[(k4*4+1)*132+o]=va.y;
    waT[(k4*4+2)*132+o]=va.z; waT[(k4*4+3)*132+o]=va.w;
    wrT[(k4*4+0)*132+o]=vr.x; wrT[(k4*4+1)*132+o]=vr.y;
    wrT[(k4*4+2)*132+o]=vr.z; wrT[(k4*4+3)*132+o]=vr.w;
  }
  __syncthreads();
  float K = (float)g_degsum/(float)n;
  float* st = stage + wid*1024;
  int j8 = ot & 7;
  int kb = (ot>>3)*32;
  int gwarp = blockIdx.x*8 + wid;
  int nbatch = (n+7)/8;
  int totw = gridDim.x*8;
  for(int b=gwarp; b<nbatch; b+=totw){
    int base = b*8;
    {
      int idx = base + j8;
      int node = g_nodelist[idx < n ? idx : n-1];
      int dg = __ldg(&degree[node]);
      float dinv = dg>0 ? 1.f/(float)dg : 0.f;
      #pragma unroll
      for(int r=0;r<8;r++){
        int kk = kb + r*4;
        float4 v = *(const float4*)&g_iagg[(size_t)node*OUTCH + kk];
        st[(kk+0)*8 + j8]=v.x*dinv; st[(kk+1)*8 + j8]=v.y*dinv;
        st[(kk+2)*8 + j8]=v.z*dinv; st[(kk+3)*8 + j8]=v.w*dinv;
      }
    }
    unsigned rmask=0, vmask=0;
    #pragma unroll
    for(int j=0;j<8;j++){
      int idx = base+j;
      if(idx<n){
        vmask |= 1u<<j;
        int nd = g_nodelist[idx];
        int dg = __ldg(&degree[nd]);
        if((float)dg < K) rmask |= 1u<<j;
      }
    }
    __syncwarp();
    #pragma unroll
    for(int pass=0; pass<2; pass++){
      unsigned sel = pass ? ((~rmask)&vmask) : (rmask&vmask);
      if(!sel) continue;
      const float* W = pass ? wrT : waT;
      unsigned long long acc2[4][4];
      #pragma unroll
      for(int i=0;i<4;i++)
        #pragma unroll
        for(int c=0;c<4;c++) acc2[i][c]=0ull;
      #pragma unroll 4
      for(int k=0;k<128;k++){
        float4 wv = *(const float4*)&W[k*132 + ot*4];
        unsigned long long wp0=pack2(wv.x,wv.x), wp1=pack2(wv.y,wv.y);
        unsigned long long wp2=pack2(wv.z,wv.z), wp3=pack2(wv.w,wv.w);
        #pragma unroll
        for(int i=0;i<4;i++){
          unsigned long long xp = *(const unsigned long long*)&st[k*8 + 2*i];
          fma2(acc2[i][0], xp, wp0);
          fma2(acc2[i][1], xp, wp1);
          fma2(acc2[i][2], xp, wp2);
          fma2(acc2[i][3], xp, wp3);
        }
      }
      float sgn = pass ? -FOMEGA : FOMEGA;
      #pragma unroll
      for(int j=0;j<8;j++){
        if(!((sel>>j)&1u)) continue;
        int nd = g_nodelist[base+j];
        int i = j>>1, p = j&1;
        float2 u0 = unpack2(acc2[i][0]);
        float2 u1 = unpack2(acc2[i][1]);
        float2 u2 = unpack2(acc2[i][2]);
        float2 u3 = unpack2(acc2[i][3]);
        float a0 = p? u0.y:u0.x;
        float a1 = p? u1.y:u1.x;
        float a2 = p? u2.y:u2.x;
        float a3 = p? u3.y:u3.x;
        int dg = __ldg(&degree[nd]);
        int dt = dg<0?0:(dg>63?63:dg);
        float4 gv = *(const float4*)&g_gamma[dt*128 + ot*4];
        float4 bv = *(const float4*)&g_beta [dt*128 + ot*4];
        float b0 = fmaf(gv.x+1.f, a0, bv.x);
        float b1 = fmaf(gv.y+1.f, a1, bv.y);
        float b2 = fmaf(gv.z+1.f, a2, bv.z);
        float b3 = fmaf(gv.w+1.f, a3, bv.w);
        float rs = g_rowsum[nd];
        float dn = 1.f/(rs + 1.00001f);
        float4 hp = *(const float4*)&g_hp[(size_t)nd*OUTCH + ot*4];
        float ss = b0*b0 + b1*b1 + b2*b2 + b3*b3;
        ss = warp_sum(ss);
        float4 ov = make_float4((hp.x + sgn*b0)*dn, (hp.y + sgn*b1)*dn,
                                (hp.z + sgn*b2)*dn, (hp.w + sgn*b3)*dn);
        *(float4*)&out[(size_t)nd*OUTCH + ot*4] = ov;
        if(ot==0) g_bselnorm[nd] = sqrtf(ss);
      }
    }
    __syncwarp();
  }
}

// ---------------- losses over idx ----------------
__global__ void loss_kernel(const int* __restrict__ idx, const int* __restrict__ degree,
                            float* __restrict__ outs, int nidx){
  float lb=0.f, lf=0.f;
  for(int j = threadIdx.x; j < nidx; j += blockDim.x){
    int nn = idx[j];
    lb += g_bselnorm[nn];
    int d = degree[nn];
    d = d < 0 ? 0 : (d > 63 ? 63 : d);
    lf += g_gnorm[d] + g_bnorm[d];
  }
  __shared__ float s1[512], s2[512];
  s1[threadIdx.x]=lb; s2[threadIdx.x]=lf;
  __syncthreads();
  for(int s=256;s>0;s>>=1){
    if(threadIdx.x<s){ s1[threadIdx.x]+=s1[threadIdx.x+s]; s2[threadIdx.x]+=s2[threadIdx.x+s]; }
    __syncthreads();
  }
  if(threadIdx.x==0){
    float inv = 1.f/(float)nidx;
    outs[0] = s1[0]*inv;
    outs[1] = s2[0]*inv;
  }
}

extern "C" void kernel_launch(void* const* d_in, const int* in_sizes, int n_in,
                              void* d_out, int out_size){
  const float* x     = (const float*)d_in[0];
  const int*   edge  = (const int*)  d_in[1];
  const float* adjv  = (const float*)d_in[2];
  const int*   degree= (const int*)  d_in[3];
  const int*   idx   = (const int*)  d_in[4];
  const float* Ww    = (const float*)d_in[5];
  const float* wbb   = (const float*)d_in[6];
  const float* av    = (const float*)d_in[7];
  const float* Wg    = (const float*)d_in[8];
  const float* Wb    = (const float*)d_in[9];
  const float* bg    = (const float*)d_in[10];
  const float* bb    = (const float*)d_in[11];
  const float* Wadd  = (const float*)d_in[12];
  const float* Wrev  = (const float*)d_in[13];
  const float* PE    = (const float*)d_in[14];
  int n    = in_sizes[0] / INCH;
  int E    = in_sizes[2];
  int nidx = in_sizes[4];
  int nhalf = n >> 1;
  float* out = (float*)d_out;
  int n2 = 2*n;
  int nb = (n2 + SCAN_B - 1)/SCAN_B;

  static cudaStream_t s_side = 0;
  static cudaEvent_t ev_fork = 0, ev_pre = 0, ev_h0 = 0, ev_agg0 = 0;
  static int made = 0;
  if(!made){
    cudaStreamCreateWithFlags(&s_side, cudaStreamNonBlocking);
    cudaEventCreateWithFlags(&ev_fork, cudaEventDisableTiming);
    cudaEventCreateWithFlags(&ev_pre,  cudaEventDisableTiming);
    cudaEventCreateWithFlags(&ev_h0,   cudaEventDisableTiming);
    cudaEventCreateWithFlags(&ev_agg0, cudaEventDisableTiming);
    made = 1;
  }

  size_t fsmem = (size_t)(2*128*132 + 8*1024)*sizeof(float);
  cudaFuncSetAttribute(finalize2_kernel, cudaFuncAttributeMaxDynamicSharedMemorySize, (int)fsmem);

  // fork: preprocessing chain on side stream
  cudaEventRecord(ev_fork, 0);
  cudaStreamWaitEvent(s_side, ev_fork, 0);

  zero_kernel<<<1184, 256, 0, s_side>>>(n);
  init_kernel<<<(n2+255)/256, 256, 0, s_side>>>(n);
  avec_kernel<<<1, 256, 0, s_side>>>(Ww, wbb, av);
  svec_kernel<<<512, 256, 0, s_side>>>(x, n);
  degsum_kernel<<<(n+255)/256, 256, 0, s_side>>>(degree, n);
  film_kernel<<<64, 128, 0, s_side>>>(PE, Wg, Wb, bg, bb);
  hist_kernel<<<(E+255)/256, 256, 0, s_side>>>(edge, E, nhalf, n);
  scan1_kernel<<<nb, SCAN_B, 0, s_side>>>(n2);
  scan2_kernel<<<1, 256, 0, s_side>>>(nb);
  scan3_kernel<<<nb, SCAN_B, 0, s_side>>>(n2, n);
  partition_kernel<<<(n+255)/256, 256, 0, s_side>>>(degree, n);
  edge_build_kernel<<<(E+255)/256, 256, 0, s_side>>>(edge, adjv, E, nhalf, n);
  cudaEventRecord(ev_pre, s_side);

  // main: gemm half 0 (h rows [0, nhalf))
  gemm_h_kernel<<<(nhalf+63)/64, 256>>>(x, Ww, wbb, 0, nhalf);
  cudaEventRecord(ev_h0, 0);

  // side: agg tile 0 (dst < nhalf) — needs preproc (ordered) + h half 0
  cudaStreamWaitEvent(s_side, ev_h0, 0);
  agg_edge_kernel<<<296, 512, 0, s_side>>>(0, E);
  cudaEventRecord(ev_agg0, s_side);

  // main: gemm half 1 runs concurrent with agg tile 0
  gemm_h_kernel<<<(n-nhalf+63)/64, 256>>>(x, Ww, wbb, nhalf, n);

  // main: agg tile 1 — needs preproc + h half 1 (ordered on main)
  cudaStreamWaitEvent(0, ev_pre, 0);
  agg_edge_kernel<<<296, 512>>>(1, E);

  // main: finalize — needs both agg tiles
  cudaStreamWaitEvent(0, ev_agg0, 0);
  finalize2_kernel<<<304, 256, fsmem>>>(Wadd, Wrev, degree, out, n);
  loss_kernel<<<1, 512>>>(idx, degree, out + (size_t)n*OUTCH, nidx);
}

// round 7
// speedup vs baseline: 1.1282x; 1.0144x over previous
#include <cuda_runtime.h>
#include <cuda_fp16.h>
#include <math.h>

#define MAXN   100000
#define MAXE   1600000
#define INCH   256
#define OUTCH  128
#define FSLOPE 0.01f
#define FOMEGA 0.1f
#define SCAN_B 1024

// ---------------- device scratch ----------------
__device__ __half g_h[MAXN*OUTCH];    // fp16 h (25.6 MB, L2-resident)
__device__ float g_iagg[MAXN*OUTCH];
__device__ float g_hp[MAXN*OUTCH];
__device__ float g_rowsum[MAXN];
__device__ float g_ssrc[MAXN];
__device__ float g_sdst[MAXN];
__device__ float g_asrc[INCH];
__device__ float g_adst[INCH];
__device__ float g_c1, g_c2;
__device__ float g_gamma[64*OUTCH];
__device__ float g_beta[64*OUTCH];
__device__ float g_gnorm[64];
__device__ float g_bnorm[64];
__device__ float g_bselnorm[MAXN];
__device__ int   g_degsum;
__device__ int   g_cntR;
__device__ int   g_cntNR;
__device__ int   g_t0end;            // # edges in tile 0 (dst < nhalf)
__device__ int   g_counts2[2*MAXN];  // [tile][src]
__device__ int   g_cursor2[2*MAXN];
__device__ int   g_bsum[256];
__device__ int   g_nodelist[MAXN];
__device__ int4  g_erec[MAXE];       // {dst, w(bits), ee(bits), src}, tile-major/src-minor

// ---------------- helpers ----------------
__device__ __forceinline__ float warp_sum(float v){
  #pragma unroll
  for(int o=16;o>0;o>>=1) v += __shfl_xor_sync(0xffffffffu, v, o);
  return v;
}
__device__ __forceinline__ int warp_sum_i(int v){
  #pragma unroll
  for(int o=16;o>0;o>>=1) v += __shfl_xor_sync(0xffffffffu, v, o);
  return v;
}
__device__ __forceinline__ unsigned long long pack2(float lo, float hi){
  unsigned long long r;
  asm("mov.b64 %0,{%1,%2};" : "=l"(r) : "f"(lo), "f"(hi));
  return r;
}
__device__ __forceinline__ void fma2(unsigned long long &d, unsigned long long a, unsigned long long b){
  asm("fma.rn.f32x2 %0, %1, %2, %0;" : "+l"(d) : "l"(a), "l"(b));
}
__device__ __forceinline__ float2 unpack2(unsigned long long p){
  float2 r;
  asm("mov.b64 {%0,%1},%2;" : "=f"(r.x), "=f"(r.y) : "l"(p));
  return r;
}
__device__ __forceinline__ void red_add_v4(float* p, float a, float b, float c, float d){
  asm volatile("red.global.add.v4.f32 [%0], {%1,%2,%3,%4};"
               :: "l"(p), "f"(a), "f"(b), "f"(c), "f"(d) : "memory");
}

// ---------------- zero accumulators ----------------
__global__ void zero_kernel(int n){
  size_t i = (size_t)blockIdx.x*blockDim.x + threadIdx.x;
  size_t stride = (size_t)gridDim.x*blockDim.x;
  float4 z = make_float4(0.f,0.f,0.f,0.f);
  float4* A = (float4*)g_iagg;
  float4* B = (float4*)g_hp;
  size_t tot4 = (size_t)n*(OUTCH/4);
  for(size_t j=i;j<tot4;j+=stride){ A[j]=z; B[j]=z; }
  for(size_t j=i;j<(size_t)n;j+=stride) g_rowsum[j]=0.f;
}

// ---------------- init counts + flags ----------------
__global__ void init_kernel(int n){
  int i = blockIdx.x*blockDim.x + threadIdx.x;
  if(i<2*n) g_counts2[i]=0;
  if(i==0){ g_degsum=0; g_cntR=0; g_cntNR=0; }
}

// ---------------- avec: asrc = sc*W^T a1, adst = sc*W^T a2, consts ----------------
__global__ void avec_kernel(const float* __restrict__ Ww, const float* __restrict__ wb,
                            const float* __restrict__ a){
  int k = threadIdx.x;  // 256
  float s1=0.f, s2=0.f;
  #pragma unroll 4
  for(int o=0;o<OUTCH;o++){
    float w = Ww[o*INCH + k];
    s1 = fmaf(w, a[o], s1);
    s2 = fmaf(w, a[OUTCH+o], s2);
  }
  const float sc = 11.313708498984761f;
  g_asrc[k] = s1*sc;
  g_adst[k] = s2*sc;
  __shared__ float c1s[256], c2s[256];
  float cb1=0.f, cb2=0.f;
  if(k<OUTCH){ float b=wb[k]; cb1 = b*a[k]; cb2 = b*a[OUTCH+k]; }
  c1s[k]=cb1; c2s[k]=cb2;
  __syncthreads();
  for(int s=128;s>0;s>>=1){
    if(k<s){ c1s[k]+=c1s[k+s]; c2s[k]+=c2s[k+s]; }
    __syncthreads();
  }
  if(k==0){ g_c1 = c1s[0]*sc; g_c2 = c2s[0]*sc; }
}

// ---------------- svec: s_src/s_dst = x @ asrc/adst + const ----------------
__global__ void __launch_bounds__(256) svec_kernel(const float* __restrict__ x, int n){
  int lane = threadIdx.x & 31;
  int gw = (blockIdx.x*blockDim.x + threadIdx.x) >> 5;
  int totw = (gridDim.x*blockDim.x) >> 5;
  const float4* A4 = (const float4*)g_asrc;
  const float4* B4 = (const float4*)g_adst;
  float4 A0 = A4[lane], A1 = A4[32+lane];
  float4 B0 = B4[lane], B1 = B4[32+lane];
  float c1 = g_c1, c2 = g_c2;
  const float4* x4 = (const float4*)x;
  for(int row=gw; row<n; row+=totw){
    float4 x0 = __ldg(&x4[(size_t)row*64 + lane]);
    float4 x1 = __ldg(&x4[(size_t)row*64 + 32 + lane]);
    float s1 = x0.x*A0.x + x0.y*A0.y + x0.z*A0.z + x0.w*A0.w
             + x1.x*A1.x + x1.y*A1.y + x1.z*A1.z + x1.w*A1.w;
    float s2 = x0.x*B0.x + x0.y*B0.y + x0.z*B0.z + x0.w*B0.w
             + x1.x*B1.x + x1.y*B1.y + x1.z*B1.z + x1.w*B1.w;
    s1 = warp_sum(s1);
    s2 = warp_sum(s2);
    if(lane==0){ g_ssrc[row]=s1+c1; g_sdst[row]=s2+c2; }
  }
}

// ---------------- degree sum ----------------
__global__ void degsum_kernel(const int* __restrict__ degree, int n){
  int i = blockIdx.x*blockDim.x + threadIdx.x;
  int v = (i<n) ? degree[i] : 0;
  v = warp_sum_i(v);
  if((threadIdx.x & 31)==0) atomicAdd(&g_degsum, v);
}

// ---------------- FiLM tables ----------------
__global__ void film_kernel(const float* __restrict__ PE, const float* __restrict__ Wg,
                            const float* __restrict__ Wb, const float* __restrict__ bg,
                            const float* __restrict__ bb){
  int d = blockIdx.x, c = threadIdx.x;
  float ga = bg[c], be = bb[c];
  #pragma unroll 4
  for(int k=0;k<128;k++){
    float p = PE[d*128+k];
    ga = fmaf(p, Wg[k*128+c], ga);
    be = fmaf(p, Wb[k*128+c], be);
  }
  ga = ga > 0.f ? ga : FSLOPE*ga;
  be = be > 0.f ? be : FSLOPE*be;
  g_gamma[d*128+c] = ga;
  g_beta [d*128+c] = be;
  __shared__ float sg[128], sb[128];
  sg[c] = ga*ga; sb[c] = be*be;
  __syncthreads();
  for(int s=64;s>0;s>>=1){
    if(c<s){ sg[c]+=sg[c+s]; sb[c]+=sb[c+s]; }
    __syncthreads();
  }
  if(c==0){ g_gnorm[d]=sqrtf(sg[0]); g_bnorm[d]=sqrtf(sb[0]); }
}

// ---------------- histogram over (tile, src) ----------------
__global__ void hist_kernel(const int* __restrict__ edge, int E, int nhalf, int n){
  int e = blockIdx.x*blockDim.x + threadIdx.x;
  if(e>=E) return;
  int src = edge[e];
  int dst = edge[E+e];
  int t = (dst >= nhalf) ? 1 : 0;
  atomicAdd(&g_counts2[t*n + src], 1);
}

// ---------------- scan (3 phases) over 2n counters ----------------
__global__ void scan1_kernel(int n2){
  __shared__ int red[32];
  int i = blockIdx.x*SCAN_B + threadIdx.x;
  int v = (i<n2)? g_counts2[i] : 0;
  int lane = threadIdx.x&31, w = threadIdx.x>>5;
  int s = warp_sum_i(v);
  if(lane==0) red[w]=s;
  __syncthreads();
  if(threadIdx.x<32){
    int t = red[threadIdx.x];
    t = warp_sum_i(t);
    if(threadIdx.x==0) g_bsum[blockIdx.x]=t;
  }
}
__global__ void scan2_kernel(int nb){   // nb <= 256, one block of 256
  __shared__ int ws[8];
  int t = threadIdx.x, lane = t&31, w = t>>5;
  int v = (t<nb)? g_bsum[t] : 0;
  int inc = v;
  #pragma unroll
  for(int o=1;o<32;o<<=1){ int u=__shfl_up_sync(0xffffffffu,inc,o); if(lane>=o) inc+=u; }
  if(lane==31) ws[w]=inc;
  __syncthreads();
  int off=0;
  #pragma unroll
  for(int i=0;i<8;i++) if(i<w) off+=ws[i];
  if(t<nb) g_bsum[t] = off + inc - v;
}
__global__ void scan3_kernel(int n2, int n){
  __shared__ int wsum[32];
  int i = blockIdx.x*SCAN_B + threadIdx.x;
  int v = (i<n2)? g_counts2[i] : 0;
  int lane = threadIdx.x&31, w = threadIdx.x>>5;
  int inc = v;
  #pragma unroll
  for(int o=1;o<32;o<<=1){ int t=__shfl_up_sync(0xffffffffu,inc,o); if(lane>=o) inc+=t; }
  if(lane==31) wsum[w]=inc;
  __syncthreads();
  if(threadIdx.x<32){
    int t = wsum[threadIdx.x];
    int sc = t;
    #pragma unroll
    for(int o=1;o<32;o<<=1){ int u=__shfl_up_sync(0xffffffffu,sc,o); if(threadIdx.x>=o) sc+=u; }
    wsum[threadIdx.x] = sc - t;
  }
  __syncthreads();
  int ex = inc - v + wsum[w] + g_bsum[blockIdx.x];
  if(i<n2) g_cursor2[i]=ex;
  if(i==n) g_t0end = ex;   // exclusive prefix at (tile1,src0) = #edges in tile 0
}

// ---------------- partition nodes by R = (deg < K) ----------------
__global__ void partition_kernel(const int* __restrict__ degree, int n){
  int i = blockIdx.x*blockDim.x + threadIdx.x;
  if(i>=n) return;
  float K = (float)g_degsum/(float)n;
  int dg = degree[i];
  if((float)dg < K){ int p=atomicAdd(&g_cntR,1);  g_nodelist[p]=i; }
  else             { int p=atomicAdd(&g_cntNR,1); g_nodelist[n-1-p]=i; }
}

// ---------------- edge build: tile-major, src-minor records ----------------
__global__ void edge_build_kernel(const int* __restrict__ edge,
    const float* __restrict__ adjv, int E, int nhalf, int n){
  int e = blockIdx.x*blockDim.x + threadIdx.x;
  if(e>=E) return;
  int src = edge[e];
  int dst = edge[E+e];
  float w  = adjv[e];
  float s = g_ssrc[src] + g_sdst[dst];
  float v = s > 0.f ? s : FSLOPE*s;
  float ee = expf(-v);
  int t = (dst >= nhalf) ? 1 : 0;
  int pos = atomicAdd(&g_cursor2[t*n + src], 1);
  g_erec[pos] = make_int4(dst, __float_as_int(w), __float_as_int(ee), src);
}

// ---------------- h = sqrt(128)*(x @ Ww^T + wb) (FFMA2), fp16 store ----------------
__global__ void __launch_bounds__(256) gemm_h_kernel(
    const float* __restrict__ x, const float* __restrict__ Ww,
    const float* __restrict__ wb, int r0, int r1){
  __shared__ float xs[32*66];
  __shared__ float wt[32*132];
  int tid = threadIdx.x;
  int ot = tid & 31, mt = tid >> 5;
  int m0 = r0 + blockIdx.x*64;
  unsigned long long acc2[4][4];
  #pragma unroll
  for(int i=0;i<4;i++)
    #pragma unroll
    for(int j=0;j<4;j++) acc2[i][j]=0ull;

  for(int kc=0;kc<8;kc++){
    #pragma unroll
    for(int i=0;i<2;i++){
      int e = tid + 256*i;
      int m = e>>3, k4 = e&7;
      int gm = m0+m;
      float4 v = make_float4(0.f,0.f,0.f,0.f);
      if(gm<r1) v = *(const float4*)&x[(size_t)gm*INCH + kc*32 + k4*4];
      xs[(k4*4+0)*66 + m]=v.x; xs[(k4*4+1)*66 + m]=v.y;
      xs[(k4*4+2)*66 + m]=v.z; xs[(k4*4+3)*66 + m]=v.w;
    }
    #pragma unroll
    for(int i=0;i<4;i++){
      int e = tid + 256*i;
      int o = e>>3, k4 = e&7;
      float4 v = *(const float4*)&Ww[(size_t)o*INCH + kc*32 + k4*4];
      wt[(k4*4+0)*132 + o]=v.x; wt[(k4*4+1)*132 + o]=v.y;
      wt[(k4*4+2)*132 + o]=v.z; wt[(k4*4+3)*132 + o]=v.w;
    }
    __syncthreads();
    #pragma unroll 4
    for(int k=0;k<32;k++){
      float4 wv = *(const float4*)&wt[k*132 + ot*4];
      unsigned long long wp0=pack2(wv.x,wv.x), wp1=pack2(wv.y,wv.y);
      unsigned long long wp2=pack2(wv.z,wv.z), wp3=pack2(wv.w,wv.w);
      #pragma unroll
      for(int i=0;i<4;i++){
        unsigned long long xp = *(const unsigned long long*)&xs[k*66 + mt*8 + 2*i];
        fma2(acc2[i][0], xp, wp0);
        fma2(acc2[i][1], xp, wp1);
        fma2(acc2[i][2], xp, wp2);
        fma2(acc2[i][3], xp, wp3);
      }
    }
    __syncthreads();
  }
  const float sc = 11.313708498984761f;
  float4 bv = *(const float4*)&wb[ot*4];
  #pragma unroll
  for(int i=0;i<4;i++){
    float2 c0 = unpack2(acc2[i][0]);
    float2 c1 = unpack2(acc2[i][1]);
    float2 c2 = unpack2(acc2[i][2]);
    float2 c3 = unpack2(acc2[i][3]);
    #pragma unroll
    for(int p=0;p<2;p++){
      int m = m0 + mt*8 + 2*i + p;
      if(m<r1){
        float h0 = ((p? c0.y:c0.x)+bv.x)*sc;
        float h1 = ((p? c1.y:c1.x)+bv.y)*sc;
        float h2 = ((p? c2.y:c2.x)+bv.z)*sc;
        float h3 = ((p? c3.y:c3.x)+bv.w)*sc;
        __half2 a01 = __floats2half2_rn(h0,h1);
        __half2 a23 = __floats2half2_rn(h2,h3);
        uint2 pv = make_uint2(*(unsigned*)&a01, *(unsigned*)&a23);
        *(uint2*)&g_h[(size_t)m*OUTCH + ot*4] = pv;
      }
    }
  }
}

// ---------------- edge-centric segmented aggregation (per dst-tile) ----------------
struct AggState {
  unsigned long long ai01, ai23, p01, p23;
  float rs;
  int cur;
};
__device__ __forceinline__ void agg_flush(AggState& st, int lane){
  float2 u0=unpack2(st.ai01), u1=unpack2(st.ai23);
  float2 v0=unpack2(st.p01),  v1=unpack2(st.p23);
  red_add_v4(&g_iagg[(size_t)st.cur*OUTCH + lane*4], u0.x,u0.y,u1.x,u1.y);
  red_add_v4(&g_hp  [(size_t)st.cur*OUTCH + lane*4], v0.x,v0.y,v1.x,v1.y);
  if(lane==0) atomicAdd(&g_rowsum[st.cur], st.rs);
}
__device__ __forceinline__ void agg_proc(AggState& st, int4 r, uint2 hv, int lane){
  if(r.w != st.cur){
    if(st.cur>=0) agg_flush(st, lane);
    st.cur=r.w; st.ai01=0ull; st.ai23=0ull; st.p01=0ull; st.p23=0ull; st.rs=0.f;
  }
  float wf = __int_as_float(r.y), ef = __int_as_float(r.z);
  float2 f01 = __half22float2(*(__half2*)&hv.x);
  float2 f23 = __half22float2(*(__half2*)&hv.y);
  unsigned long long h01=pack2(f01.x,f01.y), h23=pack2(f23.x,f23.y);
  unsigned long long wp=pack2(wf,wf), ep=pack2(ef,ef);
  fma2(st.ai01,h01,wp); fma2(st.ai23,h23,wp);
  fma2(st.p01, h01,ep); fma2(st.p23, h23,ep);
  st.rs += ef;
}
__global__ void __launch_bounds__(512) agg_edge_kernel(int tile, int E){
  int t0 = g_t0end;
  int e_lo = tile ? t0 : 0;
  int e_hi = tile ? E  : t0;
  int nE = e_hi - e_lo;
  if(nE <= 0) return;
  int lane = threadIdx.x & 31;
  int gw = (blockIdx.x*blockDim.x + threadIdx.x) >> 5;
  int totw = (gridDim.x*blockDim.x) >> 5;
  int C = (((nE + totw - 1)/totw) + 3) & ~3;
  int e0 = e_lo + gw*C;
  int e1 = min(e_hi, e0 + C);
  if(e0 >= e1) return;
  AggState st; st.cur = -1; st.ai01=0; st.ai23=0; st.p01=0; st.p23=0; st.rs=0.f;
  int q = e0;
  for(; q+4<=e1; q+=4){
    int4 r0 = __ldg(&g_erec[q+0]);
    int4 r1 = __ldg(&g_erec[q+1]);
    int4 r2 = __ldg(&g_erec[q+2]);
    int4 r3 = __ldg(&g_erec[q+3]);
    uint2 h0 = *(const uint2*)&g_h[(size_t)r0.x*OUTCH + lane*4];
    uint2 h1 = *(const uint2*)&g_h[(size_t)r1.x*OUTCH + lane*4];
    uint2 h2 = *(const uint2*)&g_h[(size_t)r2.x*OUTCH + lane*4];
    uint2 h3 = *(const uint2*)&g_h[(size_t)r3.x*OUTCH + lane*4];
    agg_proc(st, r0, h0, lane);
    agg_proc(st, r1, h1, lane);
    agg_proc(st, r2, h2, lane);
    agg_proc(st, r3, h3, lane);
  }
  for(; q<e1; q++){
    int4 r0 = __ldg(&g_erec[q]);
    uint2 h0 = *(const uint2*)&g_h[(size_t)r0.x*OUTCH + lane*4];
    agg_proc(st, r0, h0, lane);
  }
  if(st.cur>=0) agg_flush(st, lane);
}

// ---------------- finalize: batched-8 selected matvec (FFMA2) ----------------
__global__ void __launch_bounds__(256) finalize2_kernel(
    const float* __restrict__ Wadd, const float* __restrict__ Wrev,
    const int* __restrict__ degree, float* __restrict__ out, int n){
  extern __shared__ float sm[];
  float* waT   = sm;                   // 128*132
  float* wrT   = sm + 128*132;         // 128*132
  float* stage = sm + 2*128*132;       // 8 warps * 1024  ([k][j8])
  int tid = threadIdx.x;
  int ot = tid & 31, wid = tid >> 5;
  #pragma unroll
  for(int i=0;i<16;i++){
    int e2 = tid + 256*i;
    int o = e2>>5, k4 = e2&31;
    float4 va = *(const float4*)&Wadd[o*128 + k4*4];
    float4 vr = *(const float4*)&Wrev[o*128 + k4*4];
    waT[(k4*4+0)*132+o]=va.x; waT[(k4*4+1)*132+o]=va.y;
    waT[(k4*4+2)*132+o]=va.z; waT[(k4*4+3)*132+o]=va.w;
    wrT[(k4*4+0)*132+o]=vr.x; wrT[(k4*4+1)*132+o]=vr.y;
    wrT[(k4*4+2)*132+o]=vr.z; wrT[(k4*4+3)*132+o]=vr.w;
  }
  __syncthreads();
  float K = (float)g_degsum/(float)n;
  float* st = stage + wid*1024;
  int j8 = ot & 7;
  int kb = (ot>>3)*32;
  int gwarp = blockIdx.x*8 + wid;
  int nbatch = (n+7)/8;
  int totw = gridDim.x*8;
  for(int b=gwarp; b<nbatch; b+=totw){
    int base = b*8;
    {
      int idx = base + j8;
      int node = g_nodelist[idx < n ? idx : n-1];
      int dg = __ldg(&degree[node]);
      float dinv = dg>0 ? 1.f/(float)dg : 0.f;
      #pragma unroll
      for(int r=0;r<8;r++){
        int kk = kb + r*4;
        float4 v = *(const float4*)&g_iagg[(size_t)node*OUTCH + kk];
        st[(kk+0)*8 + j8]=v.x*dinv; st[(kk+1)*8 + j8]=v.y*dinv;
        st[(kk+2)*8 + j8]=v.z*dinv; st[(kk+3)*8 + j8]=v.w*dinv;
      }
    }
    unsigned rmask=0, vmask=0;
    #pragma unroll
    for(int j=0;j<8;j++){
      int idx = base+j;
      if(idx<n){
        vmask |= 1u<<j;
        int nd = g_nodelist[idx];
        int dg = __ldg(&degree[nd]);
        if((float)dg < K) rmask |= 1u<<j;
      }
    }
    __syncwarp();
    #pragma unroll
    for(int pass=0; pass<2; pass++){
      unsigned sel = pass ? ((~rmask)&vmask) : (rmask&vmask);
      if(!sel) continue;
      const float* W = pass ? wrT : waT;
      unsigned long long acc2[4][4];
      #pragma unroll
      for(int i=0;i<4;i++)
        #pragma unroll
        for(int c=0;c<4;c++) acc2[i][c]=0ull;
      #pragma unroll 4
      for(int k=0;k<128;k++){
        float4 wv = *(const float4*)&W[k*132 + ot*4];
        unsigned long long wp0=pack2(wv.x,wv.x), wp1=pack2(wv.y,wv.y);
        unsigned long long wp2=pack2(wv.z,wv.z), wp3=pack2(wv.w,wv.w);
        #pragma unroll
        for(int i=0;i<4;i++){
          unsigned long long xp = *(const unsigned long long*)&st[k*8 + 2*i];
          fma2(acc2[i][0], xp, wp0);
          fma2(acc2[i][1], xp, wp1);
          fma2(acc2[i][2], xp, wp2);
          fma2(acc2[i][3], xp, wp3);
        }
      }
      float sgn = pass ? -FOMEGA : FOMEGA;
      #pragma unroll
      for(int j=0;j<8;j++){
        if(!((sel>>j)&1u)) continue;
        int nd = g_nodelist[base+j];
        int i = j>>1, p = j&1;
        float2 u0 = unpack2(acc2[i][0]);
        float2 u1 = unpack2(acc2[i][1]);
        float2 u2 = unpack2(acc2[i][2]);
        float2 u3 = unpack2(acc2[i][3]);
        float a0 = p? u0.y:u0.x;
        float a1 = p? u1.y:u1.x;
        float a2 = p? u2.y:u2.x;
        float a3 = p? u3.y:u3.x;
        int dg = __ldg(&degree[nd]);
        int dt = dg<0?0:(dg>63?63:dg);
        float4 gv = *(const float4*)&g_gamma[dt*128 + ot*4];
        float4 bv = *(const float4*)&g_beta [dt*128 + ot*4];
        float b0 = fmaf(gv.x+1.f, a0, bv.x);
        float b1 = fmaf(gv.y+1.f, a1, bv.y);
        float b2 = fmaf(gv.z+1.f, a2, bv.z);
        float b3 = fmaf(gv.w+1.f, a3, bv.w);
        float rs = g_rowsum[nd];
        float dn = 1.f/(rs + 1.00001f);
        float4 hp = *(const float4*)&g_hp[(size_t)nd*OUTCH + ot*4];
        float ss = b0*b0 + b1*b1 + b2*b2 + b3*b3;
        ss = warp_sum(ss);
        float4 ov = make_float4((hp.x + sgn*b0)*dn, (hp.y + sgn*b1)*dn,
                                (hp.z + sgn*b2)*dn, (hp.w + sgn*b3)*dn);
        *(float4*)&out[(size_t)nd*OUTCH + ot*4] = ov;
        if(ot==0) g_bselnorm[nd] = sqrtf(ss);
      }
    }
    __syncwarp();
  }
}

// ---------------- losses over idx ----------------
__global__ void loss_kernel(const int* __restrict__ idx, const int* __restrict__ degree,
                            float* __restrict__ outs, int nidx){
  float lb=0.f, lf=0.f;
  for(int j = threadIdx.x; j < nidx; j += blockDim.x){
    int nn = idx[j];
    lb += g_bselnorm[nn];
    int d = degree[nn];
    d = d < 0 ? 0 : (d > 63 ? 63 : d);
    lf += g_gnorm[d] + g_bnorm[d];
  }
  __shared__ float s1[512], s2[512];
  s1[threadIdx.x]=lb; s2[threadIdx.x]=lf;
  __syncthreads();
  for(int s=256;s>0;s>>=1){
    if(threadIdx.x<s){ s1[threadIdx.x]+=s1[threadIdx.x+s]; s2[threadIdx.x]+=s2[threadIdx.x+s]; }
    __syncthreads();
  }
  if(threadIdx.x==0){
    float inv = 1.f/(float)nidx;
    outs[0] = s1[0]*inv;
    outs[1] = s2[0]*inv;
  }
}

extern "C" void kernel_launch(void* const* d_in, const int* in_sizes, int n_in,
                              void* d_out, int out_size){
  const float* x     = (const float*)d_in[0];
  const int*   edge  = (const int*)  d_in[1];
  const float* adjv  = (const float*)d_in[2];
  const int*   degree= (const int*)  d_in[3];
  const int*   idx   = (const int*)  d_in[4];
  const float* Ww    = (const float*)d_in[5];
  const float* wbb   = (const float*)d_in[6];
  const float* av    = (const float*)d_in[7];
  const float* Wg    = (const float*)d_in[8];
  const float* Wb    = (const float*)d_in[9];
  const float* bg    = (const float*)d_in[10];
  const float* bb    = (const float*)d_in[11];
  const float* Wadd  = (const float*)d_in[12];
  const float* Wrev  = (const float*)d_in[13];
  const float* PE    = (const float*)d_in[14];
  int n    = in_sizes[0] / INCH;
  int E    = in_sizes[2];
  int nidx = in_sizes[4];
  int nhalf = n >> 1;
  float* out = (float*)d_out;
  int n2 = 2*n;
  int nb = (n2 + SCAN_B - 1)/SCAN_B;

  static cudaStream_t s_side = 0;
  static cudaEvent_t ev_fork = 0, ev_pre = 0, ev_h0 = 0, ev_agg0 = 0;
  static int made = 0;
  if(!made){
    cudaStreamCreateWithFlags(&s_side, cudaStreamNonBlocking);
    cudaEventCreateWithFlags(&ev_fork, cudaEventDisableTiming);
    cudaEventCreateWithFlags(&ev_pre,  cudaEventDisableTiming);
    cudaEventCreateWithFlags(&ev_h0,   cudaEventDisableTiming);
    cudaEventCreateWithFlags(&ev_agg0, cudaEventDisableTiming);
    made = 1;
  }

  size_t fsmem = (size_t)(2*128*132 + 8*1024)*sizeof(float);
  cudaFuncSetAttribute(finalize2_kernel, cudaFuncAttributeMaxDynamicSharedMemorySize, (int)fsmem);

  // fork: preprocessing chain on side stream
  cudaEventRecord(ev_fork, 0);
  cudaStreamWaitEvent(s_side, ev_fork, 0);

  zero_kernel<<<1184, 256, 0, s_side>>>(n);
  init_kernel<<<(n2+255)/256, 256, 0, s_side>>>(n);
  avec_kernel<<<1, 256, 0, s_side>>>(Ww, wbb, av);
  svec_kernel<<<512, 256, 0, s_side>>>(x, n);
  degsum_kernel<<<(n+255)/256, 256, 0, s_side>>>(degree, n);
  film_kernel<<<64, 128, 0, s_side>>>(PE, Wg, Wb, bg, bb);
  hist_kernel<<<(E+255)/256, 256, 0, s_side>>>(edge, E, nhalf, n);
  scan1_kernel<<<nb, SCAN_B, 0, s_side>>>(n2);
  scan2_kernel<<<1, 256, 0, s_side>>>(nb);
  scan3_kernel<<<nb, SCAN_B, 0, s_side>>>(n2, n);
  partition_kernel<<<(n+255)/256, 256, 0, s_side>>>(degree, n);
  edge_build_kernel<<<(E+255)/256, 256, 0, s_side>>>(edge, adjv, E, nhalf, n);
  cudaEventRecord(ev_pre, s_side);

  // main: gemm half 0 (h rows [0, nhalf))
  gemm_h_kernel<<<(nhalf+63)/64, 256>>>(x, Ww, wbb, 0, nhalf);
  cudaEventRecord(ev_h0, 0);

  // side: agg tile 0 (dst < nhalf) — needs preproc (ordered) + h half 0
  cudaStreamWaitEvent(s_side, ev_h0, 0);
  agg_edge_kernel<<<296, 512, 0, s_side>>>(0, E);
  cudaEventRecord(ev_agg0, s_side);

  // main: gemm half 1 runs concurrent with agg tile 0
  gemm_h_kernel<<<(n-nhalf+63)/64, 256>>>(x, Ww, wbb, nhalf, n);

  // main: agg tile 1 — needs preproc + h half 1 (ordered on main)
  cudaStreamWaitEvent(0, ev_pre, 0);
  agg_edge_kernel<<<296, 512>>>(1, E);

  // main: finalize — needs both agg tiles
  cudaStreamWaitEvent(0, ev_agg0, 0);
  finalize2_kernel<<<304, 256, fsmem>>>(Wadd, Wrev, degree, out, n);
  loss_kernel<<<1, 512>>>(idx, degree, out + (size_t)n*OUTCH, nidx);
}